// round 6
// baseline (speedup 1.0000x reference)
#include <cuda_runtime.h>
#include <cuda_bf16.h>
#include <cstdint>

#define CIN  256
#define COUT 256
#define HDIM 64
#define WDIM 64
#define HW   4096
#define BATCH 8
#define WSZ  (256 * 256)
#define XYSZ ((size_t)BATCH * CIN * HW)

// Quantization scales (inputs ~N(0,1), weights ~N(0,1)*0.0884; clamped)
#define RX 6.0f
#define RW 0.45f
#define S1X (RX / 127.0f)
#define S1W (RW / 127.0f)
#define RATIO 254.0f

// Scratch (device globals; alloc-free rule).
__device__ __align__(128) float g_q[(size_t)BATCH * COUT * HW];
__device__ __align__(128) float g_k[(size_t)BATCH * COUT * HW];
__device__ __align__(128) float g_v[(size_t)BATCH * COUT * HW];
__device__ __align__(128) signed char g_w1[3 * WSZ];
__device__ __align__(128) signed char g_w2[3 * WSZ];
__device__ __align__(128) signed char g_xt1[XYSZ];   // transposed [b][hw][ci]
__device__ __align__(128) signed char g_xt2[XYSZ];
__device__ __align__(128) signed char g_yt1[XYSZ];
__device__ __align__(128) signed char g_yt2[XYSZ];

// ---------------------------------------------------------------------------
// helpers
// ---------------------------------------------------------------------------
__device__ __forceinline__ int q8(float x, float inv_s) {
    return __float2int_rn(fminf(fmaxf(x * inv_s, -127.0f), 127.0f));
}
__device__ __forceinline__ uint32_t pack4(int a, int b, int c, int d) {
    return (uint32_t)(a & 255) | ((uint32_t)(b & 255) << 8) |
           ((uint32_t)(c & 255) << 16) | ((uint32_t)(d & 255) << 24);
}

#define LDSM_X4(r0, r1, r2, r3, addr)                                           \
    asm volatile("ldmatrix.sync.aligned.m8n8.x4.shared.b16 {%0,%1,%2,%3}, [%4];"\
                 : "=r"(r0), "=r"(r1), "=r"(r2), "=r"(r3) : "r"(addr))

#define MMAS8(d, a, b0, b1)                                                     \
    asm volatile("mma.sync.aligned.m16n8k32.row.col.s32.s8.s8.s32 "             \
        "{%0,%1,%2,%3}, {%4,%5,%6,%7}, {%8,%9}, {%0,%1,%2,%3};"                 \
        : "+r"((d)[0]), "+r"((d)[1]), "+r"((d)[2]), "+r"((d)[3])                \
        : "r"((a)[0]), "r"((a)[1]), "r"((a)[2]), "r"((a)[3]),                   \
          "r"(b0), "r"(b1))

#define CP16(dst, src)                                                          \
    asm volatile("cp.async.cg.shared.global [%0], [%1], 16;"                    \
                 :: "r"(dst), "l"(src) : "memory")
#define CP_COMMIT asm volatile("cp.async.commit_group;" ::: "memory")
#define CP_WAIT1  asm volatile("cp.async.wait_group 1;" ::: "memory")

// SMEM stage geometry: 4 planes (A1,A2,B1,B2) of 128 rows x 48B (32 data + pad)
#define PLANE_SZ 6144
#define STAGE_SZ (4 * PLANE_SZ)     // 24576
#define GEMM_SMEM (3 * STAGE_SZ)    // 73728

// ---------------------------------------------------------------------------
// Prep: quantize W (row-major, k-contiguous) into int8 hi/lo planes.
// grid (64, 3), 256 threads; each thread one float4.
// ---------------------------------------------------------------------------
__global__ __launch_bounds__(256)
void prep_w(const float* __restrict__ wq, const float* __restrict__ wk,
            const float* __restrict__ wv)
{
    const int z = blockIdx.y;
    const float* src = (z == 0) ? wq : (z == 1 ? wk : wv);
    const int i4 = blockIdx.x * 256 + threadIdx.x;
    const float4 a = *(const float4*)(src + i4 * 4);
    const float inv1 = 1.0f / S1W, inv2 = RATIO / S1W;
    int q1[4], q2[4];
    const float v[4] = {a.x, a.y, a.z, a.w};
    #pragma unroll
    for (int j = 0; j < 4; j++) {
        q1[j] = q8(v[j], inv1);
        const float e = fmaf((float)(-q1[j]), S1W, v[j]);
        q2[j] = q8(e, inv2);
    }
    *(uint32_t*)(g_w1 + z * WSZ + i4 * 4) = pack4(q1[0], q1[1], q1[2], q1[3]);
    *(uint32_t*)(g_w2 + z * WSZ + i4 * 4) = pack4(q2[0], q2[1], q2[2], q2[3]);
}

// ---------------------------------------------------------------------------
// Prep: quantize + transpose x/y into [b][hw][ci] int8 hi/lo planes.
// grid (HW/64, CIN/64, 16): z = b + 8*tensor. 256 threads; 64x64 tile.
// ---------------------------------------------------------------------------
__global__ __launch_bounds__(256)
void prep_xy(const float* __restrict__ x, const float* __restrict__ y)
{
    __shared__ unsigned char q1s[64][68];
    __shared__ unsigned char q2s[64][68];

    const int t   = threadIdx.x;
    const int hw0 = blockIdx.x * 64;
    const int ci0 = blockIdx.y * 64;
    const int bb  = blockIdx.z & 7;
    const int tz  = blockIdx.z >> 3;       // 0 = x, 1 = y
    const float* src = tz ? y : x;
    signed char* d1 = tz ? g_yt1 : g_xt1;
    signed char* d2 = tz ? g_yt2 : g_xt2;

    const float inv1 = 1.0f / S1X, inv2 = RATIO / S1X;

    // Load + quantize: thread t -> ci row i = t/4, hw seg = (t%4)*16
    {
        const int i   = t >> 2;
        const int seg = (t & 3) * 16;
        const float* row = src + ((size_t)bb * CIN + ci0 + i) * HW + hw0 + seg;
        #pragma unroll
        for (int u = 0; u < 4; u++) {
            const float4 a = *(const float4*)(row + u * 4);
            const float v[4] = {a.x, a.y, a.z, a.w};
            int q1[4], q2[4];
            #pragma unroll
            for (int j = 0; j < 4; j++) {
                q1[j] = q8(v[j], inv1);
                const float e = fmaf((float)(-q1[j]), S1X, v[j]);
                q2[j] = q8(e, inv2);
            }
            *(uint32_t*)&q1s[i][seg + u * 4] = pack4(q1[0], q1[1], q1[2], q1[3]);
            *(uint32_t*)&q2s[i][seg + u * 4] = pack4(q2[0], q2[1], q2[2], q2[3]);
        }
    }
    __syncthreads();

    // Transposed write: thread t -> hw row jj = t/4, ci seg = (t%4)*16
    {
        const int jj  = t >> 2;
        const int seg = (t & 3) * 16;
        uint32_t w1[4], w2[4];
        #pragma unroll
        for (int u4 = 0; u4 < 4; u4++) {
            const int c = seg + u4 * 4;
            w1[u4] = pack4(q1s[c][jj], q1s[c + 1][jj], q1s[c + 2][jj], q1s[c + 3][jj]);
            w2[u4] = pack4(q2s[c][jj], q2s[c + 1][jj], q2s[c + 2][jj], q2s[c + 3][jj]);
        }
        const size_t off = ((size_t)bb * HW + hw0 + jj) * 256 + ci0 + seg;
        *(uint4*)(d1 + off) = make_uint4(w1[0], w1[1], w1[2], w1[3]);
        *(uint4*)(d2 + off) = make_uint4(w2[0], w2[1], w2[2], w2[3]);
    }
}

// ---------------------------------------------------------------------------
// int8 GEMM: C[o,p] = sum_i W[o,i]*X[i,p], 3-term int8 split, 2 s32 accums.
// 128x128 tile, 512 threads (16 warps, 32x32 warp tiles), K-chunks of 32,
// 3-stage cp.async pipeline. blockIdx.z: 0=q(y), 1=k(x), 2=v(x).
// ---------------------------------------------------------------------------
__device__ __forceinline__ void issue_stage_i8(
    uint32_t st, const signed char* __restrict__ w1,
    const signed char* __restrict__ w2, const signed char* __restrict__ b1,
    const signed char* __restrict__ b2, int m0, int k0, size_t boff, int t)
{
    const int p   = t >> 8;            // plane 0/1
    const int rem = t & 255;
    const int rr  = rem >> 1;          // row 0..127
    const int off = (rem & 1) * 16;
    const signed char* wsrc = p ? w2 : w1;
    const signed char* bsrc = p ? b2 : b1;
    CP16(st + p * PLANE_SZ + rr * 48 + off,
         wsrc + (size_t)(m0 + rr) * 256 + k0 + off);
    CP16(st + 2 * PLANE_SZ + p * PLANE_SZ + rr * 48 + off,
         bsrc + boff + (size_t)rr * 256 + k0 + off);
}

__global__ __launch_bounds__(512, 1)
void qkv_gemm_i8(const float* dummy)
{
    extern __shared__ __align__(16) char smem[];
    const uint32_t sb = (uint32_t)__cvta_generic_to_shared(smem);

    const int z = blockIdx.z;
    const signed char* w1 = g_w1 + z * WSZ;
    const signed char* w2 = g_w2 + z * WSZ;
    const signed char* b1 = (z == 0) ? g_yt1 : g_xt1;
    const signed char* b2 = (z == 0) ? g_yt2 : g_xt2;
    float* C = (z == 0) ? g_q : (z == 1 ? g_k : g_v);

    const int n0  = blockIdx.x * 128;
    const int m0  = blockIdx.y * 128;
    const int b   = n0 >> 12;
    const int hw0 = n0 & 4095;
    const size_t boff = ((size_t)b * HW + hw0) * 256;   // B: [pixel][ci]
    float* Cb = C + (size_t)b * COUT * HW + hw0;

    const int tid  = threadIdx.x;
    const int lane = tid & 31;
    const int wid  = tid >> 5;
    const int wm   = (wid >> 2) * 32;
    const int wn   = (wid & 3) * 32;
    const int jj   = lane >> 3;        // ldmatrix tile index
    const int rr   = lane & 7;         // ldmatrix row-in-tile

    int acc_hh[2][4][4], acc_xx[2][4][4];
    #pragma unroll
    for (int i = 0; i < 2; i++)
        #pragma unroll
        for (int j = 0; j < 4; j++)
            #pragma unroll
            for (int q = 0; q < 4; q++) { acc_hh[i][j][q] = 0; acc_xx[i][j][q] = 0; }

    issue_stage_i8(sb, w1, w2, b1, b2, m0, 0, boff, tid);
    CP_COMMIT;
    issue_stage_i8(sb + STAGE_SZ, w1, w2, b1, b2, m0, 32, boff, tid);
    CP_COMMIT;

    for (int it = 0; it < 8; it++) {
        CP_WAIT1;
        __syncthreads();
        if (it < 6) {
            issue_stage_i8(sb + ((it + 2) % 3) * STAGE_SZ, w1, w2, b1, b2,
                           m0, (it + 2) * 32, boff, tid);
            CP_COMMIT;
        }

        const uint32_t st = sb + (it % 3) * STAGE_SZ;
        uint32_t a1[2][4], a2[2][4], bf1[2][4], bf2[2][4];

        // A fragments: tiles j: row-half = j&1, k-half = j>>1
        #pragma unroll
        for (int mt = 0; mt < 2; mt++) {
            const uint32_t ar = st + (wm + mt * 16 + (jj & 1) * 8 + rr) * 48 + (jj >> 1) * 16;
            LDSM_X4(a1[mt][0], a1[mt][1], a1[mt][2], a1[mt][3], ar);
            LDSM_X4(a2[mt][0], a2[mt][1], a2[mt][2], a2[mt][3], ar + PLANE_SZ);
        }
        // B fragments: tiles j: n-half = j>>1, k-half = j&1
        #pragma unroll
        for (int nt = 0; nt < 2; nt++) {
            const uint32_t br = st + 2 * PLANE_SZ +
                (wn + nt * 16 + (jj >> 1) * 8 + rr) * 48 + (jj & 1) * 16;
            LDSM_X4(bf1[nt][0], bf1[nt][1], bf1[nt][2], bf1[nt][3], br);
            LDSM_X4(bf2[nt][0], bf2[nt][1], bf2[nt][2], bf2[nt][3], br + PLANE_SZ);
        }

        #pragma unroll
        for (int mt = 0; mt < 2; mt++) {
            #pragma unroll
            for (int np = 0; np < 4; np++) {
                const uint32_t p1lo = bf1[np >> 1][(np & 1) * 2];
                const uint32_t p1hi = bf1[np >> 1][(np & 1) * 2 + 1];
                const uint32_t p2lo = bf2[np >> 1][(np & 1) * 2];
                const uint32_t p2hi = bf2[np >> 1][(np & 1) * 2 + 1];
                MMAS8(acc_hh[mt][np], a1[mt], p1lo, p1hi);
                MMAS8(acc_xx[mt][np], a1[mt], p2lo, p2hi);
                MMAS8(acc_xx[mt][np], a2[mt], p1lo, p1hi);
            }
        }
    }

    // ---- Epilogue: out = S*(hh + xx/254) ----
    const float S  = S1W * S1X;
    const float Sx = S / RATIO;
    #pragma unroll
    for (int mt = 0; mt < 2; mt++) {
        const int m = wm + mt * 16 + (lane >> 2);
        #pragma unroll
        for (int np = 0; np < 4; np++) {
            const int n = wn + np * 8 + (lane & 3) * 2;
            const int* hh = acc_hh[mt][np];
            const int* xx = acc_xx[mt][np];
            const float f0 = fmaf((float)xx[0], Sx, (float)hh[0] * S);
            const float f1 = fmaf((float)xx[1], Sx, (float)hh[1] * S);
            const float f2 = fmaf((float)xx[2], Sx, (float)hh[2] * S);
            const float f3 = fmaf((float)xx[3], Sx, (float)hh[3] * S);
            *(float2*)(Cb + (size_t)(m0 + m) * HW + n)     = make_float2(f0, f1);
            *(float2*)(Cb + (size_t)(m0 + m + 8) * HW + n) = make_float2(f2, f3);
        }
    }
}

// ---------------------------------------------------------------------------
// Window attention: SMEM-tiled, 4 px/thread, zero halo, no max-subtraction.
// ---------------------------------------------------------------------------
__global__ __launch_bounds__(256)
void attn_kernel2(const float* __restrict__ rel_h, const float* __restrict__ rel_w,
                  float* __restrict__ out)
{
    __shared__ float Ks[18][68];
    __shared__ float Vs[18][68];

    const int tid = threadIdx.x;
    const int h0  = blockIdx.x * 16;
    const int c   = blockIdx.y;
    const int b   = blockIdx.z;
    const size_t plane = ((size_t)b * COUT + c) * HW;
    const float* kp = g_k + plane;
    const float* vp = g_v + plane;

    for (int i = tid; i < 18 * 16; i += 256) {
        const int r = i >> 4, f4 = i & 15;
        const int gh = h0 - 1 + r;
        float4 kv = make_float4(0.f, 0.f, 0.f, 0.f);
        float4 vv = make_float4(0.f, 0.f, 0.f, 0.f);
        if ((unsigned)gh < (unsigned)HDIM) {
            kv = *(const float4*)(kp + gh * WDIM + f4 * 4);
            vv = *(const float4*)(vp + gh * WDIM + f4 * 4);
        }
        const int j = f4 * 4 + 1;
        Ks[r][j] = kv.x; Ks[r][j + 1] = kv.y; Ks[r][j + 2] = kv.z; Ks[r][j + 3] = kv.w;
        Vs[r][j] = vv.x; Vs[r][j + 1] = vv.y; Vs[r][j + 2] = vv.z; Vs[r][j + 3] = vv.w;
    }
    if (tid < 18) {
        Ks[tid][0] = 0.f; Ks[tid][65] = 0.f;
        Vs[tid][0] = 0.f; Vs[tid][65] = 0.f;
    }

    float b9[9];
    {
        const bool use_h = (c < 128);
        float bias[3];
        if (use_h) {
            bias[0] = rel_h[c * 3 + 0]; bias[1] = rel_h[c * 3 + 1]; bias[2] = rel_h[c * 3 + 2];
        } else {
            bias[0] = rel_w[(c - 128) * 3 + 0]; bias[1] = rel_w[(c - 128) * 3 + 1];
            bias[2] = rel_w[(c - 128) * 3 + 2];
        }
        #pragma unroll
        for (int dr = 0; dr < 3; dr++)
            #pragma unroll
            for (int dj = 0; dj < 3; dj++)
                b9[dr * 3 + dj] = use_h ? bias[dr] : bias[dj];
    }
    __syncthreads();

    const int lr = tid >> 4;
    const int w0 = (tid & 15) * 4;
    const int h  = h0 + lr;

    const float4 q4 = *(const float4*)(g_q + plane + h * WDIM + w0);
    const float q[4] = {q4.x, q4.y, q4.z, q4.w};

    float kk[3][6], vv[3][6];
    #pragma unroll
    for (int dr = 0; dr < 3; dr++) {
        const float* krow = &Ks[lr + dr][w0];
        const float* vrow = &Vs[lr + dr][w0];
        const float4 ka = *(const float4*)krow;
        const float2 kb = *(const float2*)(krow + 4);
        const float4 va = *(const float4*)vrow;
        const float2 vb = *(const float2*)(vrow + 4);
        kk[dr][0] = ka.x; kk[dr][1] = ka.y; kk[dr][2] = ka.z;
        kk[dr][3] = ka.w; kk[dr][4] = kb.x; kk[dr][5] = kb.y;
        vv[dr][0] = va.x; vv[dr][1] = va.y; vv[dr][2] = va.z;
        vv[dr][3] = va.w; vv[dr][4] = vb.x; vv[dr][5] = vb.y;
    }

    float res[4];
    #pragma unroll
    for (int p = 0; p < 4; p++) {
        float den = 0.f, num = 0.f;
        #pragma unroll
        for (int dr = 0; dr < 3; dr++)
            #pragma unroll
            for (int dj = 0; dj < 3; dj++) {
                const float e = __expf(q[p] * (kk[dr][p + dj] + b9[dr * 3 + dj]));
                den += e;
                num = fmaf(e, vv[dr][p + dj], num);
            }
        res[p] = __fdividef(num, den);
    }

    *(float4*)(out + plane + h * WDIM + w0) = make_float4(res[0], res[1], res[2], res[3]);
}

// ---------------------------------------------------------------------------
extern "C" void kernel_launch(void* const* d_in, const int* in_sizes, int n_in,
                              void* d_out, int out_size)
{
    const float* x     = (const float*)d_in[0];
    const float* y     = (const float*)d_in[1];
    const float* wq    = (const float*)d_in[2];
    const float* wk    = (const float*)d_in[3];
    const float* wv    = (const float*)d_in[4];
    const float* rel_h = (const float*)d_in[5];
    const float* rel_w = (const float*)d_in[6];
    float* out = (float*)d_out;

    cudaFuncSetAttribute(qkv_gemm_i8, cudaFuncAttributeMaxDynamicSharedMemorySize,
                         GEMM_SMEM);

    prep_w<<<dim3(64, 3), 256>>>(wq, wk, wv);
    prep_xy<<<dim3(HW / 64, CIN / 64, 16), 256>>>(x, y);

    dim3 ggrid(BATCH * HW / 128, COUT / 128, 3);   // (256, 2, 3)
    qkv_gemm_i8<<<ggrid, 512, GEMM_SMEM>>>(nullptr);

    dim3 agrid(HDIM / 16, COUT, BATCH);            // (4, 256, 8)
    attn_kernel2<<<agrid, 256>>>(rel_h, rel_w, out);
}

// round 7
// speedup vs baseline: 3.3205x; 3.3205x over previous
#include <cuda_runtime.h>
#include <cuda_fp16.h>
#include <cstdint>

#define CIN  256
#define COUT 256
#define HDIM 64
#define WDIM 64
#define HW   4096
#define BATCH 8

// Scratch for q, k, v (33.5MB each) — static device globals (alloc-free rule).
__device__ __align__(128) float g_q[(size_t)BATCH * COUT * HW];
__device__ __align__(128) float g_k[(size_t)BATCH * COUT * HW];
__device__ __align__(128) float g_v[(size_t)BATCH * COUT * HW];

// ---------------------------------------------------------------------------
// helpers
// ---------------------------------------------------------------------------
// fp32 pair -> packed f16x2 (low 16 bits = a, high = b)
__device__ __forceinline__ uint32_t f2h2(float a, float b) {
    uint32_t r;
    asm("cvt.rn.f16x2.f32 %0, %1, %2;" : "=r"(r) : "f"(b), "f"(a));
    return r;
}

#define LDSM_X4(r0, r1, r2, r3, addr)                                           \
    asm volatile("ldmatrix.sync.aligned.m8n8.x4.shared.b16 {%0,%1,%2,%3}, [%4];"\
                 : "=r"(r0), "=r"(r1), "=r"(r2), "=r"(r3) : "r"(addr))

#define LDSM_X4_T(r0, r1, r2, r3, addr)                                         \
    asm volatile("ldmatrix.sync.aligned.m8n8.x4.trans.shared.b16 {%0,%1,%2,%3}, [%4];"\
                 : "=r"(r0), "=r"(r1), "=r"(r2), "=r"(r3) : "r"(addr))

#define MMAF16(d, a, b0, b1)                                                    \
    asm volatile("mma.sync.aligned.m16n8k16.row.col.f32.f16.f16.f32 "           \
        "{%0,%1,%2,%3}, {%4,%5,%6,%7}, {%8,%9}, {%0,%1,%2,%3};"                 \
        : "+f"((d)[0]), "+f"((d)[1]), "+f"((d)[2]), "+f"((d)[3])                \
        : "r"((a)[0]), "r"((a)[1]), "r"((a)[2]), "r"((a)[3]),                   \
          "r"(b0), "r"(b1))

#define A_STRIDE 40     // f16 elems per row of 128x32 A tile (80B, padded)
#define B_STRIDE 136    // f16 elems per row of 32x128 B tile (272B, padded)

// ---------------------------------------------------------------------------
// GEMM: C[o,p] = sum_i W[o,i] * X[i,p] per batch image, single-term fp16 MMA.
// Block tile 128(M) x 128(N), K-blocks of 32, double-buffered SMEM with
// register-staged global loads. 256 threads, 8 warps (32x64 warp tiles).
// blockIdx.z: 0 = q(wq,y), 1 = k(wk,x), 2 = v(wv,x).
// ---------------------------------------------------------------------------
__global__ __launch_bounds__(256)
void qkv_gemm_fp16(const float* __restrict__ wq, const float* __restrict__ wk,
                   const float* __restrict__ wv, const float* __restrict__ x,
                   const float* __restrict__ y)
{
    __shared__ __align__(16) __half As[2][128 * A_STRIDE];   // 2 x 10240 B
    __shared__ __align__(16) __half Bs[2][32 * B_STRIDE];    // 2 x  8704 B

    const int z = blockIdx.z;
    const float* Wm = (z == 0) ? wq : (z == 1 ? wk : wv);
    const float* X  = (z == 0) ? y : x;
    float*       C  = (z == 0) ? g_q : (z == 1 ? g_k : g_v);

    const int n0  = blockIdx.x * 128;
    const int m0  = blockIdx.y * 128;
    const int b   = n0 >> 12;
    const int hw0 = n0 & 4095;
    const float* Xb = X + (size_t)b * CIN * HW + hw0;
    float*       Cb = C + (size_t)b * COUT * HW + hw0;

    const int tid  = threadIdx.x;
    const int lane = tid & 31;
    const int wid  = tid >> 5;
    const int wm   = (wid >> 1) * 32;   // warp m offset (0,32,64,96)
    const int wn   = (wid & 1) * 64;    // warp n offset (0,64)

    // A-load mapping: 4 float4/thread
    const int acol = (tid & 7) * 4;     // 0..28
    const int arow = tid >> 3;          // 0..31 (+32*i)
    // B-load mapping: 4 float4/thread
    const int bcol = (tid & 31) * 4;    // 0..124
    const int brow = tid >> 5;          // 0..7 (+8*i)

    float acc[2][8][4];
    #pragma unroll
    for (int i = 0; i < 2; i++)
        #pragma unroll
        for (int j = 0; j < 8; j++)
            #pragma unroll
            for (int q = 0; q < 4; q++)
                acc[i][j][q] = 0.0f;

    float4 ra[4], rb[4];

    // ---- prologue: load + convert + store k-block 0 into buffer 0 ----
    #pragma unroll
    for (int i = 0; i < 4; i++)
        ra[i] = *(const float4*)(Wm + (size_t)(m0 + arow + i * 32) * CIN + acol);
    #pragma unroll
    for (int i = 0; i < 4; i++)
        rb[i] = *(const float4*)(Xb + (size_t)(brow + i * 8) * HW + bcol);
    #pragma unroll
    for (int i = 0; i < 4; i++) {
        *(uint2*)((char*)As[0] + (arow + i * 32) * 80 + acol * 2) =
            make_uint2(f2h2(ra[i].x, ra[i].y), f2h2(ra[i].z, ra[i].w));
        *(uint2*)((char*)Bs[0] + (brow + i * 8) * 272 + bcol * 2) =
            make_uint2(f2h2(rb[i].x, rb[i].y), f2h2(rb[i].z, rb[i].w));
    }
    __syncthreads();

    for (int it = 0; it < 8; it++) {
        // Issue next k-block's global loads early (latency hidden by MMAs)
        if (it < 7) {
            const int k0 = (it + 1) * 32;
            #pragma unroll
            for (int i = 0; i < 4; i++)
                ra[i] = *(const float4*)(Wm + (size_t)(m0 + arow + i * 32) * CIN + k0 + acol);
            #pragma unroll
            for (int i = 0; i < 4; i++)
                rb[i] = *(const float4*)(Xb + (size_t)(k0 + brow + i * 8) * HW + bcol);
        }

        // ---- Compute: 2 ksteps of 16 from buffer it&1 ----
        const uint32_t sA = (uint32_t)__cvta_generic_to_shared(As[it & 1]);
        const uint32_t sB = (uint32_t)__cvta_generic_to_shared(Bs[it & 1]);
        #pragma unroll
        for (int ks = 0; ks < 2; ks++) {
            const int kb = ks * 16;
            uint32_t af[2][4];
            #pragma unroll
            for (int mt = 0; mt < 2; mt++) {
                const uint32_t off =
                    (uint32_t)((wm + mt * 16 + (lane & 15)) * A_STRIDE + kb + (lane >> 4) * 8) * 2;
                LDSM_X4(af[mt][0], af[mt][1], af[mt][2], af[mt][3], sA + off);
            }
            #pragma unroll
            for (int ntp = 0; ntp < 4; ntp++) {
                const int nb = wn + ntp * 16;
                const uint32_t off =
                    (uint32_t)((kb + (lane & 15)) * B_STRIDE + nb + (lane >> 4) * 8) * 2;
                uint32_t bf[4];
                LDSM_X4_T(bf[0], bf[1], bf[2], bf[3], sB + off);
                #pragma unroll
                for (int mt = 0; mt < 2; mt++) {
                    #pragma unroll
                    for (int h2 = 0; h2 < 2; h2++)
                        MMAF16(acc[mt][ntp * 2 + h2], af[mt], bf[h2 * 2], bf[h2 * 2 + 1]);
                }
            }
        }

        // Convert + store next k-block into the other buffer
        if (it < 7) {
            __half* dA = As[(it + 1) & 1];
            __half* dB = Bs[(it + 1) & 1];
            #pragma unroll
            for (int i = 0; i < 4; i++) {
                *(uint2*)((char*)dA + (arow + i * 32) * 80 + acol * 2) =
                    make_uint2(f2h2(ra[i].x, ra[i].y), f2h2(ra[i].z, ra[i].w));
                *(uint2*)((char*)dB + (brow + i * 8) * 272 + bcol * 2) =
                    make_uint2(f2h2(rb[i].x, rb[i].y), f2h2(rb[i].z, rb[i].w));
            }
        }
        __syncthreads();
    }

    // ---- Epilogue ----
    #pragma unroll
    for (int mt = 0; mt < 2; mt++) {
        const int m = wm + mt * 16 + (lane >> 2);
        #pragma unroll
        for (int nt = 0; nt < 8; nt++) {
            const int n = wn + nt * 8 + (lane & 3) * 2;
            const float* d = acc[mt][nt];
            *(float2*)(Cb + (size_t)(m0 + m) * HW + n)     = make_float2(d[0], d[1]);
            *(float2*)(Cb + (size_t)(m0 + m + 8) * HW + n) = make_float2(d[2], d[3]);
        }
    }
}

// ---------------------------------------------------------------------------
// Window attention: SMEM-tiled, 4 px/thread, zero halo, no max-subtraction
// (logits bounded |l| << 88, denominator cannot fully underflow).
// ---------------------------------------------------------------------------
__global__ __launch_bounds__(256)
void attn_kernel2(const float* __restrict__ rel_h, const float* __restrict__ rel_w,
                  float* __restrict__ out)
{
    __shared__ float Ks[18][68];
    __shared__ float Vs[18][68];

    const int tid = threadIdx.x;
    const int h0  = blockIdx.x * 16;
    const int c   = blockIdx.y;
    const int b   = blockIdx.z;
    const size_t plane = ((size_t)b * COUT + c) * HW;
    const float* kp = g_k + plane;
    const float* vp = g_v + plane;

    for (int i = tid; i < 18 * 16; i += 256) {
        const int r = i >> 4, f4 = i & 15;
        const int gh = h0 - 1 + r;
        float4 kv = make_float4(0.f, 0.f, 0.f, 0.f);
        float4 vv = make_float4(0.f, 0.f, 0.f, 0.f);
        if ((unsigned)gh < (unsigned)HDIM) {
            kv = *(const float4*)(kp + gh * WDIM + f4 * 4);
            vv = *(const float4*)(vp + gh * WDIM + f4 * 4);
        }
        const int j = f4 * 4 + 1;
        Ks[r][j] = kv.x; Ks[r][j + 1] = kv.y; Ks[r][j + 2] = kv.z; Ks[r][j + 3] = kv.w;
        Vs[r][j] = vv.x; Vs[r][j + 1] = vv.y; Vs[r][j + 2] = vv.z; Vs[r][j + 3] = vv.w;
    }
    if (tid < 18) {
        Ks[tid][0] = 0.f; Ks[tid][65] = 0.f;
        Vs[tid][0] = 0.f; Vs[tid][65] = 0.f;
    }

    float b9[9];
    {
        const bool use_h = (c < 128);
        float bias[3];
        if (use_h) {
            bias[0] = rel_h[c * 3 + 0]; bias[1] = rel_h[c * 3 + 1]; bias[2] = rel_h[c * 3 + 2];
        } else {
            bias[0] = rel_w[(c - 128) * 3 + 0]; bias[1] = rel_w[(c - 128) * 3 + 1];
            bias[2] = rel_w[(c - 128) * 3 + 2];
        }
        #pragma unroll
        for (int dr = 0; dr < 3; dr++)
            #pragma unroll
            for (int dj = 0; dj < 3; dj++)
                b9[dr * 3 + dj] = use_h ? bias[dr] : bias[dj];
    }
    __syncthreads();

    const int lr = tid >> 4;
    const int w0 = (tid & 15) * 4;
    const int h  = h0 + lr;

    const float4 q4 = *(const float4*)(g_q + plane + h * WDIM + w0);
    const float q[4] = {q4.x, q4.y, q4.z, q4.w};

    float kk[3][6], vv[3][6];
    #pragma unroll
    for (int dr = 0; dr < 3; dr++) {
        const float* krow = &Ks[lr + dr][w0];
        const float* vrow = &Vs[lr + dr][w0];
        const float4 ka = *(const float4*)krow;
        const float2 kb = *(const float2*)(krow + 4);
        const float4 va = *(const float4*)vrow;
        const float2 vb = *(const float2*)(vrow + 4);
        kk[dr][0] = ka.x; kk[dr][1] = ka.y; kk[dr][2] = ka.z;
        kk[dr][3] = ka.w; kk[dr][4] = kb.x; kk[dr][5] = kb.y;
        vv[dr][0] = va.x; vv[dr][1] = va.y; vv[dr][2] = va.z;
        vv[dr][3] = va.w; vv[dr][4] = vb.x; vv[dr][5] = vb.y;
    }

    float res[4];
    #pragma unroll
    for (int p = 0; p < 4; p++) {
        float den = 0.f, num = 0.f;
        #pragma unroll
        for (int dr = 0; dr < 3; dr++)
            #pragma unroll
            for (int dj = 0; dj < 3; dj++) {
                const float e = __expf(q[p] * (kk[dr][p + dj] + b9[dr * 3 + dj]));
                den += e;
                num = fmaf(e, vv[dr][p + dj], num);
            }
        res[p] = __fdividef(num, den);
    }

    *(float4*)(out + plane + h * WDIM + w0) = make_float4(res[0], res[1], res[2], res[3]);
}

// ---------------------------------------------------------------------------
extern "C" void kernel_launch(void* const* d_in, const int* in_sizes, int n_in,
                              void* d_out, int out_size)
{
    const float* x     = (const float*)d_in[0];
    const float* y     = (const float*)d_in[1];
    const float* wq    = (const float*)d_in[2];
    const float* wk    = (const float*)d_in[3];
    const float* wv    = (const float*)d_in[4];
    const float* rel_h = (const float*)d_in[5];
    const float* rel_w = (const float*)d_in[6];
    float* out = (float*)d_out;

    dim3 ggrid(BATCH * HW / 128, COUT / 128, 3);   // (256, 2, 3)
    qkv_gemm_fp16<<<ggrid, 256>>>(wq, wk, wv, x, y);

    dim3 agrid(HDIM / 16, COUT, BATCH);            // (4, 256, 8)
    attn_kernel2<<<agrid, 256>>>(rel_h, rel_w, out);
}